// round 9
// baseline (speedup 1.0000x reference)
#include <cuda_runtime.h>

// HierarchicalPooling: the reference's _sinkhorn_log updates v LAST:
//   v = log_b - lse_s(Klog + u)
// so sum_s exp(u + v + Klog) = exp(v + lse_s(u + Klog)) = exp(log_b) = b.
// The pooled marginal equals the target marginal b = 1/K + 1e-12 exactly,
// independent of the data, in BOTH Sinkhorn stages; after normalization the
// output is the constant 1/K_ATOMS = 1/64 everywhere (empty graphs too).
// Verified across 6 rounds: rel_err = 4.2e-7, launch-overhead bound.
//
// Geometry scan (ncu kernel time, clean 5-instr body):
//   8x128 = 3.07-3.36us (best, harness 4.608 stable)
//   1x1024 = 3.52us, 16x64 = 3.62us
// This round: final unmeasured cell, 4x256 with the clean body (R1's 4x256
// carried guard/tail SASS and isn't comparable). Expected neutral; decides
// the final config.

__global__ void __launch_bounds__(256, 1)
HP_fill_4x256(float4* __restrict__ out4) {
    const float v = 0.015625f;  // 1/64
    // 4 blocks x 256 threads, one 16B store each -> 4096 floats exactly.
    out4[blockIdx.x * 256u + threadIdx.x] = make_float4(v, v, v, v);
}

// Generic guarded fallback (never used for this problem's fixed shape).
__global__ void HP_fill_generic(float* __restrict__ out, int n) {
    const float v = 0.015625f;
    int i = blockIdx.x * blockDim.x + threadIdx.x;
    if (i < n) out[i] = v;
}

extern "C" void kernel_launch(void* const* d_in, const int* in_sizes, int n_in,
                              void* d_out, int out_size) {
    (void)d_in; (void)in_sizes; (void)n_in;
    if (out_size == 4096) {
        HP_fill_4x256<<<4, 256>>>((float4*)d_out);
    } else {
        int threads = 256;
        int blocks = (out_size + threads - 1) / threads;
        HP_fill_generic<<<blocks, threads>>>((float*)d_out, out_size);
    }
}

// round 10
// speedup vs baseline: 1.1875x; 1.1875x over previous
#include <cuda_runtime.h>

// HierarchicalPooling — FINAL.
//
// Algebraic identity: the reference's _sinkhorn_log updates v LAST:
//   v = log_b - lse_s(Klog + u)
// so for the returned (u, v):
//   sum_s exp(u + v + Klog) = exp(v + lse_s(u + Klog)) = exp(log_b) = b.
// The pooled marginal equals the target marginal b = 1/K + 1e-12 EXACTLY,
// independent of the input data, in BOTH Sinkhorn stages (node histograms
// and graph histograms). After normalization the output is the constant
// 1/K_ATOMS = 1/64 everywhere; empty graphs are explicitly set to 1/K too.
// Measured rel_err vs reference: 4.19e-7 (reference's own fp32 rounding).
//
// Geometry scan (clean body: IMAD + STG.E.128 + EXIT, 16 regs):
//   8x128  : ncu 3.07-3.36us, harness 4.608us  <-- optimum, reproduced 2x
//   4x256  : ncu 3.14us,      harness 5.47us
//   1x1024 : ncu 3.52us,      harness 4.90us
//   16x64  : ncu 3.62us,      harness outlier
// Kernel is purely launch-latency bound (DRAM 0.0%, all pipes idle); the
// 16KB of stores cost ~2ns of HBM time. No further kernel-side lever exists.

__global__ void __launch_bounds__(128, 1)
HP_fill_exact(float4* __restrict__ out4) {
    const float v = 0.015625f;  // 1/64
    // 8 blocks x 128 threads, one 16B store each -> 4096 floats exactly.
    out4[blockIdx.x * 128u + threadIdx.x] = make_float4(v, v, v, v);
}

// Generic guarded fallback (never used for this problem's fixed shape).
__global__ void HP_fill_generic(float* __restrict__ out, int n) {
    const float v = 0.015625f;
    int i = blockIdx.x * blockDim.x + threadIdx.x;
    if (i < n) out[i] = v;
}

extern "C" void kernel_launch(void* const* d_in, const int* in_sizes, int n_in,
                              void* d_out, int out_size) {
    (void)d_in; (void)in_sizes; (void)n_in;
    if (out_size == 4096) {
        HP_fill_exact<<<8, 128>>>((float4*)d_out);
    } else {
        int threads = 256;
        int blocks = (out_size + threads - 1) / threads;
        HP_fill_generic<<<blocks, threads>>>((float*)d_out, out_size);
    }
}